// round 1
// baseline (speedup 1.0000x reference)
#include <cuda_runtime.h>

// TpsGridGen: theta (64, 50) -> grid (64, 256, 192, 2) fp32
//
// Strategy:
//  - TPS system matrix L (28x28) and its inverse depend only on the fixed 5x5
//    control grid -> computed at COMPILE TIME (constexpr fp64 Gauss-Jordan with
//    partial pivoting + constexpr log). Baked into __constant__ memory.
//  - Kernel 1 (tiny): per-batch coefficients [W;A] = Li[:,:25] @ (theta + P),
//    stored as (x,y) float2 pairs.
//  - Kernel 2 (main): one thread per pixel (per batch-half). Computes the 25
//    RBF values U_n = d2*log(d2) ONCE, then accumulates the (x,y) output pair
//    with packed fma.rn.f32x2 over 28 coefficient pairs per batch.

#define OUT_H 256
#define OUT_W 192
#define NCP   25
#define NB    64
#define NCOEF 28   // 25 RBF + [1, gx, gy] affine

// ---------------------------------------------------------------------------
// Compile-time constants: control points + first 25 columns of inv(L), fp32
// ---------------------------------------------------------------------------
struct TPSConst {
    float li[NCOEF][NCP];
    float px[NCP];
    float py[NCP];
};

constexpr double cfabs(double x) { return x < 0.0 ? -x : x; }

// Accurate constexpr natural log (range reduction + atanh series).
constexpr double clog(double x) {
    int e = 0;
    while (x >= 1.4142135623730951) { x *= 0.5; e++; }
    while (x <  0.7071067811865476) { x *= 2.0; e--; }
    double t  = (x - 1.0) / (x + 1.0);
    double t2 = t * t;
    double p = t, s = 0.0;
    for (int k = 0; k < 27; k++) { s += p / (double)(2 * k + 1); p *= t2; }
    return 2.0 * s + (double)e * 0.6931471805599453094172321214581766;
}

constexpr TPSConst make_tps() {
    TPSConst r{};
    const double ax[5] = {-1.0, -0.5, 0.0, 0.5, 1.0};
    double PX[NCP] = {}, PY[NCP] = {};
    // P_Y, P_X = np.meshgrid(ax, ax) -> P_X[k] = ax[k/5], P_Y[k] = ax[k%5]
    for (int i = 0; i < 5; i++)
        for (int j = 0; j < 5; j++) { PX[i * 5 + j] = ax[i]; PY[i * 5 + j] = ax[j]; }

    // Augmented [L | I] (28 x 56)
    double a[28][56] = {};
    for (int i = 0; i < 25; i++)
        for (int j = 0; j < 25; j++) {
            if (i == j) { a[i][j] = 0.0; }   // d2==0 -> 1*log(1) = 0
            else {
                double dx = PX[i] - PX[j], dy = PY[i] - PY[j];
                double d2 = dx * dx + dy * dy;
                a[i][j] = d2 * clog(d2);
            }
        }
    for (int i = 0; i < 25; i++) {
        a[i][25] = 1.0; a[i][26] = PX[i]; a[i][27] = PY[i];
        a[25][i] = 1.0; a[26][i] = PX[i]; a[27][i] = PY[i];
    }
    for (int i = 0; i < 28; i++) a[i][28 + i] = 1.0;

    // Gauss-Jordan with partial pivoting (L has a zero diagonal block).
    for (int k = 0; k < 28; k++) {
        int piv = k; double best = cfabs(a[k][k]);
        for (int i = k + 1; i < 28; i++) {
            double v = cfabs(a[i][k]);
            if (v > best) { best = v; piv = i; }
        }
        if (piv != k)
            for (int j = 0; j < 56; j++) {
                double tmp = a[k][j]; a[k][j] = a[piv][j]; a[piv][j] = tmp;
            }
        double inv = 1.0 / a[k][k];
        for (int j = 0; j < 56; j++) a[k][j] *= inv;
        for (int i = 0; i < 28; i++) {
            if (i == k) continue;
            double f = a[i][k];
            if (f != 0.0)
                for (int j = 0; j < 56; j++) a[i][j] -= f * a[k][j];
        }
    }
    for (int n = 0; n < NCOEF; n++)
        for (int m = 0; m < NCP; m++)
            r.li[n][m] = (float)a[n][28 + m];
    for (int i = 0; i < NCP; i++) { r.px[i] = (float)PX[i]; r.py[i] = (float)PY[i]; }
    return r;
}

constexpr TPSConst H_TPS = make_tps();
__constant__ TPSConst c_tps = H_TPS;

// ---------------------------------------------------------------------------
// Scratch: per-batch coefficient pairs (Wx,Wy) for n=0..24, (A c,cx,cy) n=25..27
// ---------------------------------------------------------------------------
__device__ __align__(16) float2 g_coef[NB * NCOEF];

__global__ void tps_coef_kernel(const float* __restrict__ theta) {
    const int b = blockIdx.x;
    const int n = threadIdx.x;
    if (n >= NCOEF) return;
    const float* t = theta + b * (2 * NCP);
    float sx = 0.f, sy = 0.f;
#pragma unroll
    for (int m = 0; m < NCP; m++) {
        const float li = c_tps.li[n][m];
        sx = fmaf(li, t[m]       + c_tps.px[m], sx);
        sy = fmaf(li, t[NCP + m] + c_tps.py[m], sy);
    }
    g_coef[b * NCOEF + n] = make_float2(sx, sy);
}

// ---------------------------------------------------------------------------
// Packed f32x2 helpers
// ---------------------------------------------------------------------------
__device__ __forceinline__ unsigned long long pack2(float lo, float hi) {
    unsigned long long r;
    asm("mov.b64 %0, {%1, %2};" : "=l"(r) : "f"(lo), "f"(hi));
    return r;
}
__device__ __forceinline__ unsigned long long fma2(unsigned long long a,
                                                   unsigned long long b,
                                                   unsigned long long c) {
    unsigned long long d;
    asm("fma.rn.f32x2 %0, %1, %2, %3;" : "=l"(d) : "l"(a), "l"(b), "l"(c));
    return d;
}

// ---------------------------------------------------------------------------
// Main kernel: grid (384, 2), block 128. Each thread: 1 pixel x 32 batches.
// ---------------------------------------------------------------------------
__global__ __launch_bounds__(128, 1) void tps_main_kernel(float2* __restrict__ out) {
    __shared__ __align__(16) float2 sc[32 * NCOEF];
    const int tid  = threadIdx.x;
    const int half = blockIdx.y;           // which 32-batch half

    // Stage this half's coefficients into shared memory (7 KB).
    {
        const float4* src = (const float4*)(g_coef + half * 32 * NCOEF);
        float4* dst = (float4*)sc;
#pragma unroll
        for (int i = 0; i < 4; i++) {
            int idx = tid + i * 128;
            if (idx < 32 * NCOEF / 2) dst[idx] = src[idx];
        }
    }

    const int pid = blockIdx.x * 128 + tid;
    const int h = pid / OUT_W;
    const int w = pid - h * OUT_W;

    // numpy linspace semantics: fp64 step, endpoint forced exact, cast fp32.
    const float gx = (w == OUT_W - 1) ? 1.0f
                     : (float)(-1.0 + (double)w * (2.0 / (double)(OUT_W - 1)));
    const float gy = (h == OUT_H - 1) ? 1.0f
                     : (float)(-1.0 + (double)h * (2.0 / (double)(OUT_H - 1)));

    // U vector, duplicated into both f32x2 lanes (shared by x and y outputs).
    unsigned long long U2[NCOEF];
#pragma unroll
    for (int n = 0; n < NCP; n++) {
        const float dx = gx - c_tps.px[n];
        const float dy = gy - c_tps.py[n];
        const float d2 = dx * dx + dy * dy;
        const float u = (d2 == 0.0f) ? 0.0f : d2 * __logf(d2);
        U2[n] = pack2(u, u);
    }
    U2[25] = pack2(1.0f, 1.0f);
    U2[26] = pack2(gx, gx);
    U2[27] = pack2(gy, gy);

    __syncthreads();

    const int bbase = half * 32;
#pragma unroll 2
    for (int bl = 0; bl < 32; bl += 2) {
        const ulonglong2* c0 = (const ulonglong2*)(sc + (bl)     * NCOEF);
        const ulonglong2* c1 = (const ulonglong2*)(sc + (bl + 1) * NCOEF);
        unsigned long long a0 = 0ull, a1 = 0ull;
#pragma unroll
        for (int q = 0; q < NCOEF / 2; q++) {
            const ulonglong2 p0 = c0[q];
            const ulonglong2 p1 = c1[q];
            a0 = fma2(U2[2 * q],     p0.x, a0);
            a0 = fma2(U2[2 * q + 1], p0.y, a0);
            a1 = fma2(U2[2 * q],     p1.x, a1);
            a1 = fma2(U2[2 * q + 1], p1.y, a1);
        }
        const int b0 = bbase + bl;
        float2 r0, r1;
        asm("mov.b64 {%0, %1}, %2;" : "=f"(r0.x), "=f"(r0.y) : "l"(a0));
        asm("mov.b64 {%0, %1}, %2;" : "=f"(r1.x), "=f"(r1.y) : "l"(a1));
        out[(size_t)(b0 * OUT_H + h) * OUT_W + w]       = r0;
        out[(size_t)((b0 + 1) * OUT_H + h) * OUT_W + w] = r1;
    }
}

// ---------------------------------------------------------------------------
extern "C" void kernel_launch(void* const* d_in, const int* in_sizes, int n_in,
                              void* d_out, int out_size) {
    const float* theta = (const float*)d_in[0];
    (void)in_sizes; (void)n_in; (void)out_size;

    tps_coef_kernel<<<NB, 32>>>(theta);

    dim3 grid(OUT_H * OUT_W / 128, 2);
    tps_main_kernel<<<grid, 128>>>((float2*)d_out);
}